// round 8
// baseline (speedup 1.0000x reference)
#include <cuda_runtime.h>

#define BATCH  16
#define H      1024
#define W      1024
#define HW     (H*W)
#define W4     256            // float4 words per row
#define NCHUNK 9
#define CHUNK  116            // even; 9*116=1044, last chunk rows=96
#define NBLK   (BATCH*NCHUNK) // 144
#define RING   36
#define RW     260            // f4 per ring slot: [0]=left guard, [1..256]=data
#define SW     264            // f4 per U snapshot: [0..3] left guard, [4..259] data, [260..263] right guard
#define SUBASE (RING*RW)      // 9360
#define F4TOT  (SUBASE + 12*SW)

__device__ float        g_accum[BATCH * 5];
__device__ unsigned int g_count;

__device__ __forceinline__ float4 f4z() { return make_float4(0.f, 0.f, 0.f, 0.f); }

__device__ __forceinline__ void epi(float x, float m, float S3, float S15, float S31,
                                    float& a0, float& a1, float& a2, float& a3, float& a4)
{
    float w = 1.f + 5.f * ( fabsf(S3  * (1.f / 9.f)   - m)
                          + fabsf(S15 * (1.f / 225.f) - m)
                          + fabsf(S31 * (1.f / 961.f) - m) );
    float e   = __expf(-fabsf(x));
    float l   = __logf(1.f + e);
    float bce = fmaxf(x, 0.f) - x * m + l;
    float inv = __fdividef(1.f, 1.f + e);
    float sg  = (x >= 0.f) ? inv : e * inv;
    a0 += w;
    a1 += w * bce;
    a2 += sg * m * w;
    a3 += (sg + m) * w;
    a4 += fabsf(sg - m);
}

__device__ __forceinline__ void addf4(float4& a, const float4 b) {
    a.x += b.x; a.y += b.y; a.z += b.z; a.w += b.w;
}

__global__ __launch_bounds__(512, 1) void adaptive_loss_main(
    const float* __restrict__ pred, const float* __restrict__ mask, float* __restrict__ out)
{
    extern __shared__ float4 sm4[];
    float* smf   = (float*)sm4;
    float* swsum = smf + (size_t)F4TOT * 4;   // 16 floats
    float* sred  = swsum + 16;                // 80 floats
    unsigned int* sflag = (unsigned int*)(sred + 80);

    const int tid  = threadIdx.x;
    const int lane = tid & 31;
    const int warp = tid >> 5;
    const int g    = tid >> 8;                // group 0/1
    const int t    = tid & 255;               // owns cols 4t..4t+3
    const int wg   = warp & 7;                // warp within group

    const int b  = blockIdx.x / NCHUNK;
    const int c  = blockIdx.x % NCHUNK;
    const int y0 = c * CHUNK;
    const int rows = (H - y0 < CHUNK) ? (H - y0) : CHUNK;
    const int NP = rows >> 1;

    const float4* mb4 = (const float4*)(mask + (size_t)b * HW);
    const float4* pb4 = (const float4*)(pred + (size_t)b * HW);

    // ---- one-time guard init ----
    if (tid < RING) sm4[tid * RW] = f4z();
    else if (tid < RING + 48) {
        int k2 = tid - RING;                   // 12 arrays x 4 left-guard words
        sm4[SUBASE + (k2 >> 2) * SW + (k2 & 3)] = f4z();
    }
    __syncthreads();

    float4 U31 = f4z(), U15 = f4z(), U3 = f4z();
    float a0 = 0.f, a1 = 0.f, a2 = 0.f, a3 = 0.f, a4 = 0.f;

    // slot of row r = (r + 720) % 36
    int spA = (y0 - 17 + 720) % 36;            // slot of pair's even row
    int spg = spA + g; if (spg >= 36) spg -= 36;

    const int lo31 = y0 - 17 + g, hi31 = y0 + 13 + g;
    const int lo15 = y0 - 9 + g,  hi15 = y0 + 5 + g;
    const int lo3  = y0 - 3 + g,  hi3  = y0 - 1 + g;

    // ================= priming: 16 pairs, rows y0-17 .. y0+14 =================
    int rP = y0 - 17 + g;
    float4 mCur = (rP >= 0) ? mb4[rP * W4 + t] : f4z();

    #pragma unroll 1
    for (int j = 0; j < 16; ++j) {
        int rN = rP + 2;                       // at j==15 loads row y0+15+g (main's first scan row)
        float4 mN = (rN >= 0) ? mb4[rN * W4 + t] : f4z();

        float4 v = mCur; v.y += v.x; v.z += v.y; v.w += v.z;
        float tot = v.w;
        #pragma unroll
        for (int d = 1; d < 32; d <<= 1) {
            float tt = __shfl_up_sync(0xffffffffu, tot, d);
            if (lane >= d) tot += tt;
        }
        if (lane == 31) swsum[g * 8 + wg] = tot;
        __syncthreads();
        float wv = (lane < 8) ? swsum[g * 8 + lane] : 0.f;
        #pragma unroll
        for (int d = 1; d < 8; d <<= 1) {
            float tt = __shfl_up_sync(0xffffffffu, wv, d);
            if (lane >= d) wv += tt;
        }
        float off = __shfl_sync(0xffffffffu, wv, (wg > 0) ? (wg - 1) : 0);
        if (wg == 0) off = 0.f;
        float bse = off + (tot - v.w);
        float4 P = make_float4(v.x + bse, v.y + bse, v.z + bse, v.w + bse);
        sm4[spg * RW + 1 + t] = P;
        __syncthreads();

        int spB = spA + 1; if (spB >= 36) spB -= 36;
        float4 PA = sm4[spA * RW + 1 + t];
        float4 PB = sm4[spB * RW + 1 + t];
        int rA = y0 - 17 + 2 * j, rB = rA + 1;
        if (rA >= lo31 && rA <= hi31) addf4(U31, PA);
        if (rB >= lo31 && rB <= hi31) addf4(U31, PB);
        if (rA >= lo15 && rA <= hi15) addf4(U15, PA);
        if (rB >= lo15 && rB <= hi15) addf4(U15, PB);
        if (rA >= lo3  && rA <= hi3 ) addf4(U3,  PA);
        if (rB >= lo3  && rB <= hi3 ) addf4(U3,  PB);

        mCur = mN; rP = rN;
        spA += 2; if (spA >= 36) spA -= 36;
        spg += 2; if (spg >= 36) spg -= 36;
    }
    // now: spg = slot(y0+15+g), mCur = mask row y0+15+g
    // U31 = sum P[y_g-17-g+... ] = U31(y_g - 2), etc.

    int sbg = spg;
    float4 pCur = f4z();

    const int k0 = g * 3;

    // ================= main: NP iterations (2 rows each) =================
    #pragma unroll 1
    for (int i = 0; i < NP; ++i) {
        // prefetch for next iteration
        int rS = y0 + 17 + g + 2 * i;
        float4 mN = (rS < H) ? mb4[rS * W4 + t] : f4z();
        float4 pN = pb4[(y0 + 2 * i + g) * W4 + t];

        // ---- phase I: scan row y_g+15+2i ----
        float4 v = mCur; v.y += v.x; v.z += v.y; v.w += v.z;
        float tot = v.w;
        #pragma unroll
        for (int d = 1; d < 32; d <<= 1) {
            float tt = __shfl_up_sync(0xffffffffu, tot, d);
            if (lane >= d) tot += tt;
        }
        if (lane == 31) swsum[g * 8 + wg] = tot;
        __syncthreads();                                   // BAR 1

        // ---- phase II: offsets, ring write ----
        float wv = (lane < 8) ? swsum[g * 8 + lane] : 0.f;
        #pragma unroll
        for (int d = 1; d < 8; d <<= 1) {
            float tt = __shfl_up_sync(0xffffffffu, wv, d);
            if (lane >= d) wv += tt;
        }
        float off = __shfl_sync(0xffffffffu, wv, (wg > 0) ? (wg - 1) : 0);
        if (wg == 0) off = 0.f;
        float bse = off + (tot - v.w);
        float4 P = make_float4(v.x + bse, v.y + bse, v.z + bse, v.w + bse);
        sm4[sbg * RW + 1 + t] = P;
        __syncthreads();                                   // BAR 2

        // ---- phase III: U updates (step by 2 rows), snapshot, consume ----
        #define SL(L_) ({ int s_ = sbg - (L_); if (s_ < 0) s_ += 36; s_; })
        int s1  = SL(1),  s31 = SL(31), s32 = SL(32);
        int s8  = SL(8),  s9  = SL(9),  s23 = SL(23), s24 = SL(24);
        int s14 = SL(14), s15 = SL(15), s17 = SL(17), s18 = SL(18);
        #undef SL

        float4 r1  = sm4[s1  * RW + 1 + t];
        float4 r31 = sm4[s31 * RW + 1 + t];
        float4 r32 = sm4[s32 * RW + 1 + t];
        float4 r8  = sm4[s8  * RW + 1 + t];
        float4 r9  = sm4[s9  * RW + 1 + t];
        float4 r23 = sm4[s23 * RW + 1 + t];
        float4 r24 = sm4[s24 * RW + 1 + t];
        float4 r14 = sm4[s14 * RW + 1 + t];
        float4 r15 = sm4[s15 * RW + 1 + t];
        float4 r17 = sm4[s17 * RW + 1 + t];    // = consume row (m source)
        float4 r18 = sm4[s18 * RW + 1 + t];

        U31.x += P.x + r1.x - r31.x - r32.x;  U31.y += P.y + r1.y - r31.y - r32.y;
        U31.z += P.z + r1.z - r31.z - r32.z;  U31.w += P.w + r1.w - r31.w - r32.w;
        U15.x += r8.x + r9.x - r23.x - r24.x; U15.y += r8.y + r9.y - r23.y - r24.y;
        U15.z += r8.z + r9.z - r23.z - r24.z; U15.w += r8.w + r9.w - r23.w - r24.w;
        U3.x  += r14.x + r15.x - r17.x - r18.x; U3.y += r14.y + r15.y - r17.y - r18.y;
        U3.z  += r14.z + r15.z - r17.z - r18.z; U3.w += r14.w + r15.w - r17.w - r18.w;

        const int par = i & 1;
        const int wb  = SUBASE + (par * 6 + k0) * SW;
        sm4[wb + 4 + t]            = U31;
        sm4[wb + SW + 4 + t]       = U15;
        sm4[wb + 2 * SW + 4 + t]   = U3;
        if (wg == 7) {
            float q31 = __shfl_sync(0xffffffffu, U31.w, 31);
            float q15 = __shfl_sync(0xffffffffu, U15.w, 31);
            float q3  = __shfl_sync(0xffffffffu, U3.w,  31);
            if (lane < 12) {
                int arr = lane >> 2;
                float qq = (arr == 0) ? q31 : (arr == 1) ? q15 : q3;
                sm4[wb + arr * SW + 260 + (lane & 3)] = make_float4(qq, qq, qq, qq);
            }
        }

        if (i > 0) {
            const int rb  = SUBASE + ((par ^ 1) * 6 + k0) * SW;
            float4 c31 = sm4[rb + t];
            float4 a31 = sm4[rb + t + 7];
            float4 b31 = sm4[rb + t + 8];
            float4 c15 = sm4[rb + SW + t + 2];
            float4 a15 = sm4[rb + SW + t + 5];
            float4 b15 = sm4[rb + SW + t + 6];
            float4 d3  = sm4[rb + 2 * SW + t + 3];
            float4 e3  = sm4[rb + 2 * SW + t + 4];
            float4 f3  = sm4[rb + 2 * SW + t + 5];

            float S31x = a31.w - c31.x, S31y = b31.x - c31.y, S31z = b31.y - c31.z, S31w = b31.z - c31.w;
            float S15x = a15.w - c15.x, S15y = b15.x - c15.y, S15z = b15.y - c15.z, S15w = b15.z - c15.w;
            float S3x  = e3.y - d3.z,   S3y  = e3.z - d3.w,   S3z  = e3.w - e3.x,   S3w  = f3.x - e3.y;

            float lw = smf[(s17 * RW + t) * 4 + 3];
            float m0 = r17.x - lw, m1 = r17.y - r17.x, m2 = r17.z - r17.y, m3 = r17.w - r17.z;

            epi(pCur.x, m0, S3x, S15x, S31x, a0, a1, a2, a3, a4);
            epi(pCur.y, m1, S3y, S15y, S31y, a0, a1, a2, a3, a4);
            epi(pCur.z, m2, S3z, S15z, S31z, a0, a1, a2, a3, a4);
            epi(pCur.w, m3, S3w, S15w, S31w, a0, a1, a2, a3, a4);
        }

        mCur = mN; pCur = pN;
        sbg += 2; if (sbg >= 36) sbg -= 36;
    }

    // ================= tail: consume pair NP-1 =================
    __syncthreads();
    {
        const int parT = (NP - 1) & 1;
        const int rb = SUBASE + (parT * 6 + k0) * SW;
        int sc = sbg - 17; if (sc < 0) sc += 36;
        float4 rw = sm4[sc * RW + 1 + t];
        float  lw = smf[(sc * RW + t) * 4 + 3];

        float4 c31 = sm4[rb + t];
        float4 a31 = sm4[rb + t + 7];
        float4 b31 = sm4[rb + t + 8];
        float4 c15 = sm4[rb + SW + t + 2];
        float4 a15 = sm4[rb + SW + t + 5];
        float4 b15 = sm4[rb + SW + t + 6];
        float4 d3  = sm4[rb + 2 * SW + t + 3];
        float4 e3  = sm4[rb + 2 * SW + t + 4];
        float4 f3  = sm4[rb + 2 * SW + t + 5];

        float S31x = a31.w - c31.x, S31y = b31.x - c31.y, S31z = b31.y - c31.z, S31w = b31.z - c31.w;
        float S15x = a15.w - c15.x, S15y = b15.x - c15.y, S15z = b15.y - c15.z, S15w = b15.z - c15.w;
        float S3x  = e3.y - d3.z,   S3y  = e3.z - d3.w,   S3z  = e3.w - e3.x,   S3w  = f3.x - e3.y;

        float m0 = rw.x - lw, m1 = rw.y - rw.x, m2 = rw.z - rw.y, m3 = rw.w - rw.z;

        epi(pCur.x, m0, S3x, S15x, S31x, a0, a1, a2, a3, a4);
        epi(pCur.y, m1, S3y, S15y, S31y, a0, a1, a2, a3, a4);
        epi(pCur.z, m2, S3z, S15z, S31z, a0, a1, a2, a3, a4);
        epi(pCur.w, m3, S3w, S15w, S31w, a0, a1, a2, a3, a4);
    }

    // ================= reduction + atomics =================
    #pragma unroll
    for (int d = 16; d > 0; d >>= 1) {
        a0 += __shfl_down_sync(0xffffffffu, a0, d);
        a1 += __shfl_down_sync(0xffffffffu, a1, d);
        a2 += __shfl_down_sync(0xffffffffu, a2, d);
        a3 += __shfl_down_sync(0xffffffffu, a3, d);
        a4 += __shfl_down_sync(0xffffffffu, a4, d);
    }
    if (lane == 0) {
        sred[warp * 5 + 0] = a0; sred[warp * 5 + 1] = a1; sred[warp * 5 + 2] = a2;
        sred[warp * 5 + 3] = a3; sred[warp * 5 + 4] = a4;
    }
    __syncthreads();
    if (warp == 0 && lane < 5) {
        float s = 0.f;
        #pragma unroll
        for (int wq = 0; wq < 16; ++wq) s += sred[wq * 5 + lane];
        atomicAdd(&g_accum[b * 5 + lane], s);
    }

    // ---- last-block finalize ----
    __threadfence();
    if (tid == 0) {
        unsigned int cdone = atomicAdd(&g_count, 1u);
        *sflag = (cdone == (unsigned int)(gridDim.x - 1)) ? 1u : 0u;
    }
    __syncthreads();
    if (*sflag && tid == 0) {
        float vals[BATCH * 5];
        #pragma unroll 1
        for (int i = 0; i < BATCH * 5; ++i) vals[i] = atomicAdd(&g_accum[i], 0.f);
        float mae_total = 0.f;
        for (int bb = 0; bb < BATCH; ++bb) mae_total += vals[bb * 5 + 4];
        const float mae = mae_total / (float)((long long)BATCH * HW);
        float acc = 0.f;
        for (int bb = 0; bb < BATCH; ++bb) {
            float ws = vals[bb * 5 + 0];
            float wb2 = vals[bb * 5 + 1];
            float it = vals[bb * 5 + 2];
            float un = vals[bb * 5 + 3];
            float wbce = wb2 / ws;
            float wiou = 1.f - (it + 1.f) / (un - it + 1.f);
            float wmae = mae * ws / (ws - (float)HW);
            acc += 0.7f * (wbce + wiou + wmae);
        }
        out[0] = acc / (float)BATCH;
        #pragma unroll 1
        for (int i = 0; i < BATCH * 5; ++i) g_accum[i] = 0.f;
        __threadfence();
        atomicExch(&g_count, 0u);
    }
}

extern "C" void kernel_launch(void* const* d_in, const int* in_sizes, int n_in,
                              void* d_out, int out_size) {
    const float* pred = (const float*)d_in[0];
    const float* mask = (const float*)d_in[1];
    float* out = (float*)d_out;

    const int smem_bytes = F4TOT * 16 + (16 + 80 + 1) * 4;
    cudaFuncSetAttribute(adaptive_loss_main,
                         cudaFuncAttributeMaxDynamicSharedMemorySize, smem_bytes);
    adaptive_loss_main<<<NBLK, 512, smem_bytes>>>(pred, mask, out);
}